// round 2
// baseline (speedup 1.0000x reference)
#include <cuda_runtime.h>
#include <cstdint>

#define DI __device__ __forceinline__

// ---------------- problem constants ----------------
namespace {
constexpr int BATCH = 128;
constexpr int NFRM  = 16;
constexpr int TPF   = 49;
constexpr int NSEL  = 8;
constexpr int TOK   = NFRM * TPF;          // 784
constexpr int MTOT  = BATCH * TOK;         // 100352
constexpr int KDIM  = 1024;
constexpr int NDIM  = 512;

constexpr int M_TILE = 256;
constexpr int N_TILE = 128;
constexpr int KC     = 32;                 // K elems per chunk (=128B row)
constexpr int NK     = KDIM / KC;          // 32
constexpr int NTHR   = 512;                // 16 warps: 4 (m) x 4 (n)
constexpr long long SEL_ELEMS = (long long)BATCH * NSEL * TPF * NDIM; // 25,690,112

// shared memory layout
constexpr int SM_A0   = 0;                 // 256 x 128B = 32KB
constexpr int SM_A1   = 32768;
constexpr int SM_B0   = 65536;             // 128 x 128B = 16KB
constexpr int SM_B1   = 81920;
constexpr int SM_BIAS = 98304;             // 128 floats (this CTA's n-block)
constexpr int SM_TOTAL = 98304 + 512;
}

#define SWZ(b) ((b) ^ (((b) >> 3) & 0x70))

// ---------------- device scratch (no runtime allocation allowed) -----------
__device__ float g_vid[(size_t)MTOT * NDIM];   // 205.5 MB vid_feats scratch
__device__ float g_wt[NDIM * KDIM];            // fc_w transposed, tf32-rounded
__device__ float g_part[4][MTOT];              // per-n-block sumsq partials
__device__ float g_ts[MTOT];                   // token_score * ||vid_feats row||
__device__ int   g_sel[BATCH * NSEL];          // selected frames, ascending

// ---------------- PTX helpers ----------------
DI uint32_t smem_u32(const void* p) {
    uint32_t a;
    asm("{ .reg .u64 t; cvta.to.shared.u64 t, %1; cvt.u32.u64 %0, t; }" : "=r"(a) : "l"(p));
    return a;
}
DI uint32_t f2tf32(float f) {
    uint32_t r;
    asm("cvt.rna.tf32.f32 %0, %1;" : "=r"(r) : "f"(f));
    return r;
}
DI void ldsm4(uint32_t (&r)[4], uint32_t addr) {
    asm volatile("ldmatrix.sync.aligned.m8n8.x4.shared.b16 {%0,%1,%2,%3}, [%4];"
                 : "=r"(r[0]), "=r"(r[1]), "=r"(r[2]), "=r"(r[3]) : "r"(addr));
}
DI void mma8(float (&d)[4], const uint32_t (&a)[4], uint32_t b0, uint32_t b1) {
    asm volatile("mma.sync.aligned.m16n8k8.row.col.f32.tf32.tf32.f32 "
                 "{%0,%1,%2,%3}, {%4,%5,%6,%7}, {%8,%9}, {%0,%1,%2,%3};"
                 : "+f"(d[0]), "+f"(d[1]), "+f"(d[2]), "+f"(d[3])
                 : "r"(a[0]), "r"(a[1]), "r"(a[2]), "r"(a[3]), "r"(b0), "r"(b1));
}
DI void cp16(uint32_t dst, const void* src) {
    asm volatile("cp.async.cg.shared.global [%0], [%1], 16;" :: "r"(dst), "l"(src) : "memory");
}
#define CP_COMMIT() asm volatile("cp.async.commit_group;" ::: "memory")
#define CP_WAIT0()  asm volatile("cp.async.wait_group 0;" ::: "memory")

// ---------------- kernel 1: transpose + tf32-round fc_w ----------------
__global__ void wt_kernel(const float* __restrict__ w) {
    __shared__ float t[32][33];
    int k0 = blockIdx.x * 32, n0 = blockIdx.y * 32;
    int x = threadIdx.x, y = threadIdx.y;
    #pragma unroll
    for (int dy = 0; dy < 32; dy += 8)
        t[y + dy][x] = w[(size_t)(k0 + y + dy) * NDIM + n0 + x];
    __syncthreads();
    #pragma unroll
    for (int dy = 0; dy < 32; dy += 8)
        g_wt[(size_t)(n0 + y + dy) * KDIM + k0 + x] = __uint_as_float(f2tf32(t[x][y + dy]));
}

// ---------------- kernel 2: tf32 mma.sync GEMM (256x128 tile) --------------
__global__ void __launch_bounds__(NTHR, 1)
gemm_kernel(const float* __restrict__ swin, const float* __restrict__ fcb) {
    extern __shared__ char smem[];
    uint32_t sb = smem_u32(smem);
    int tid = threadIdx.x;
    int w = tid >> 5, l = tid & 31;
    int nb = blockIdx.x;
    int m0 = blockIdx.y * M_TILE;
    int gn0 = nb * N_TILE;
    int wm = (w >> 2) * 64;        // warp m offset (0,64,128,192)
    int wn = (w & 3) * 32;         // warp n offset (0,32,64,96)

    // bias for this n-block
    if (tid < N_TILE) *(float*)(smem + SM_BIAS + tid * 4) = fcb[gn0 + tid];

    float acc[4][4][4];
    #pragma unroll
    for (int mt = 0; mt < 4; mt++)
        #pragma unroll
        for (int nt = 0; nt < 4; nt++)
            #pragma unroll
            for (int j = 0; j < 4; j++) acc[mt][nt][j] = 0.f;

    // per-lane ldmatrix row byte-offsets within tile
    uint32_t lx   = (uint32_t)(l & 7);
    uint32_t apar = (uint32_t)(l >> 4);          // A chunk parity
    uint32_t bpar = (uint32_t)((l >> 3) & 1);    // B chunk parity
    uint32_t a_off[4], b_off[2];
    {
        uint32_t arow = (uint32_t)(wm + (l & 15));
        #pragma unroll
        for (int mt = 0; mt < 4; mt++) a_off[mt] = (arow + mt * 16) * 128u;
        uint32_t brow = (uint32_t)(wn + (l & 7) + ((l & 16) >> 1));
        #pragma unroll
        for (int g = 0; g < 2; g++) b_off[g] = (brow + g * 16) * 128u;
    }

    // ---- load chunk 0 ----
    #pragma unroll
    for (int s = 0; s < 4; s++) {
        int slot = tid + s * NTHR;
        int row = slot >> 3, q = slot & 7;
        float4 v = *(const float4*)(swin + (size_t)(m0 + row) * KDIM + q * 4);
        uint4 t;
        t.x = f2tf32(v.x); t.y = f2tf32(v.y); t.z = f2tf32(v.z); t.w = f2tf32(v.w);
        *(uint4*)(smem + SM_A0 + row * 128 + ((q ^ (row & 7)) << 4)) = t;
    }
    #pragma unroll
    for (int s = 0; s < 2; s++) {
        int slot = tid + s * NTHR;
        int row = slot >> 3, q = slot & 7;
        cp16(sb + SM_B0 + row * 128 + ((q ^ (row & 7)) << 4),
             g_wt + (size_t)(gn0 + row) * KDIM + q * 4);
    }
    CP_COMMIT();
    CP_WAIT0();
    __syncthreads();

    int buf = 0;
    float4 pa[4];
    for (int i = 0; i < NK; i++) {
        int k0n = (i + 1) * KC;
        if (i + 1 < NK) {
            // prefetch A (needs cvt) into regs; B straight to other buffer
            #pragma unroll
            for (int s = 0; s < 4; s++) {
                int slot = tid + s * NTHR;
                int row = slot >> 3, q = slot & 7;
                pa[s] = *(const float4*)(swin + (size_t)(m0 + row) * KDIM + k0n + q * 4);
            }
            uint32_t bdst = sb + (buf ? SM_B0 : SM_B1);
            #pragma unroll
            for (int s = 0; s < 2; s++) {
                int slot = tid + s * NTHR;
                int row = slot >> 3, q = slot & 7;
                cp16(bdst + row * 128 + ((q ^ (row & 7)) << 4),
                     g_wt + (size_t)(gn0 + row) * KDIM + k0n + q * 4);
            }
            CP_COMMIT();
        }

        // ---- compute chunk i ----
        uint32_t ab = sb + (buf ? SM_A1 : SM_A0);
        uint32_t bb = sb + (buf ? SM_B1 : SM_B0);
        #pragma unroll
        for (int ks = 0; ks < 4; ks++) {
            uint32_t af[4][4], bfr[2][4];
            uint32_t ca = ((2u * ks + apar) ^ lx) << 4;
            uint32_t cb = ((2u * ks + bpar) ^ lx) << 4;
            #pragma unroll
            for (int mt = 0; mt < 4; mt++) ldsm4(af[mt], ab + a_off[mt] + ca);
            #pragma unroll
            for (int g = 0; g < 2; g++)  ldsm4(bfr[g], bb + b_off[g] + cb);
            #pragma unroll
            for (int mt = 0; mt < 4; mt++)
                #pragma unroll
                for (int nt = 0; nt < 4; nt++)
                    mma8(acc[mt][nt], af[mt],
                         bfr[nt >> 1][(nt & 1) * 2], bfr[nt >> 1][(nt & 1) * 2 + 1]);
        }

        if (i + 1 < NK) {
            char* abuf = smem + (buf ? SM_A0 : SM_A1);
            #pragma unroll
            for (int s = 0; s < 4; s++) {
                int slot = tid + s * NTHR;
                int row = slot >> 3, q = slot & 7;
                uint4 t;
                t.x = f2tf32(pa[s].x); t.y = f2tf32(pa[s].y);
                t.z = f2tf32(pa[s].z); t.w = f2tf32(pa[s].w);
                *(uint4*)(abuf + row * 128 + ((q ^ (row & 7)) << 4)) = t;
            }
            CP_WAIT0();
            __syncthreads();
            buf ^= 1;
        }
    }

    // ---- epilogue: bias, vid write, per-row sumsq ----
    const float* sbias = (const float*)(smem + SM_BIAS);
    float* part = (float*)smem;    // reuse A0 region: [256][4] floats
    #pragma unroll
    for (int mt = 0; mt < 4; mt++) {
        int r0 = wm + mt * 16 + (l >> 2);
        float s0 = 0.f, s1 = 0.f;
        #pragma unroll
        for (int nt = 0; nt < 4; nt++) {
            int colL = wn + nt * 8 + (l & 3) * 2;
            float b0 = sbias[colL], b1 = sbias[colL + 1];
            float v0 = acc[mt][nt][0] + b0, v1 = acc[mt][nt][1] + b1;
            float v2 = acc[mt][nt][2] + b0, v3 = acc[mt][nt][3] + b1;
            s0 += v0 * v0 + v1 * v1;
            s1 += v2 * v2 + v3 * v3;
            size_t g0 = (size_t)(m0 + r0) * NDIM + gn0 + colL;
            *(float2*)(g_vid + g0) = make_float2(v0, v1);
            *(float2*)(g_vid + g0 + 8 * NDIM) = make_float2(v2, v3);
        }
        s0 += __shfl_xor_sync(0xFFFFFFFFu, s0, 1);
        s0 += __shfl_xor_sync(0xFFFFFFFFu, s0, 2);
        s1 += __shfl_xor_sync(0xFFFFFFFFu, s1, 1);
        s1 += __shfl_xor_sync(0xFFFFFFFFu, s1, 2);
        if ((l & 3) == 0) {
            part[r0 * 4 + (w & 3)] = s0;
            part[(r0 + 8) * 4 + (w & 3)] = s1;
        }
    }
    __syncthreads();
    if (tid < M_TILE) {
        float s = part[tid * 4] + part[tid * 4 + 1] + part[tid * 4 + 2] + part[tid * 4 + 3];
        g_part[nb][m0 + tid] = s;
    }
}

// ---------------- kernel 2b: finish token scores ----------------
__global__ void ts_kernel(const float* __restrict__ tsc) {
    int t = blockIdx.x * 256 + threadIdx.x;
    if (t < MTOT) {
        float s = g_part[0][t] + g_part[1][t] + g_part[2][t] + g_part[3][t];
        g_ts[t] = tsc[t] * sqrtf(s);
    }
}

// ---------------- kernel 3: frame scores + gumbel selection ----------------
__global__ void select_kernel(const float* __restrict__ gumbel,
                              float* __restrict__ out, long long out_elems) {
    __shared__ float tsh[TOK];
    __shared__ float fsh[NFRM];
    int b = blockIdx.x, t = threadIdx.x;
    tsh[t] = g_ts[b * TOK + t];
    __syncthreads();
    if (t < NFRM) {
        float s = 0.f;
        #pragma unroll
        for (int j = 0; j < TPF; j++) s += tsh[t * TPF + j];
        fsh[t] = s;
    }
    __syncthreads();
    if (t == 0) {
        const float NEG_INF = __int_as_float(0xff800000);
        float tot = 0.f;
        for (int f = 0; f < NFRM; f++) tot += fsh[f];
        float fs[NFRM], sc[NFRM], sel[NFRM];
        for (int f = 0; f < NFRM; f++) { fs[f] = fsh[f] / tot; sc[f] = fs[f]; sel[f] = 0.f; }
        for (int s = 0; s < NSEL; s++) {
            const float* g = gumbel + ((size_t)s * BATCH + b) * NFRM;
            float best = NEG_INF; int bi = 0;
            for (int f = 0; f < NFRM; f++) {
                float v = (sel[f] > 0.f) ? NEG_INF : (sc[f] + g[f]);
                if (v > best) { best = v; bi = f; }   // strict > == first-max argmax
            }
            sel[bi] = 1.f; sc[bi] = 0.f;
        }
        float rest = 0.f;
        for (int f = 0; f < NFRM; f++) rest += fs[f] * (1.f - sel[f]);
        float label = (rest >= 0.5f) ? 1.f : 0.f;
        int c = 0;
        for (int f = 0; f < NFRM; f++)
            if (sel[f] > 0.f) g_sel[b * NSEL + (c++)] = f;     // ascending
        if (out_elems >= SEL_ELEMS + BATCH + (long long)BATCH * NFRM) {
            out[SEL_ELEMS + b] = label;
            float* fsp = out + SEL_ELEMS + BATCH;
            for (int f = 0; f < NFRM; f++) fsp[b * NFRM + f] = sel[f];
        }
    }
}

// ---------------- kernel 4: gather selected frames ----------------
__global__ void gather_kernel(float* __restrict__ out) {
    int j = blockIdx.x, b = blockIdx.y;
    int f = g_sel[b * NSEL + j];
    const float4* src = (const float4*)(g_vid + ((size_t)b * TOK + (size_t)f * TPF) * NDIM);
    float4* dst = (float4*)(out + ((size_t)b * (NSEL * TPF) + (size_t)j * TPF) * NDIM);
    constexpr int N4 = TPF * NDIM / 4;   // 6272
    for (int i = threadIdx.x; i < N4; i += blockDim.x) dst[i] = src[i];
}

// ---------------- launch ----------------
extern "C" void kernel_launch(void* const* d_in, const int* in_sizes, int n_in,
                              void* d_out, int out_size) {
    const float* swin = (const float*)d_in[0];   // (128, 784, 1024)
    const float* fcw  = (const float*)d_in[1];   // (1024, 512)
    const float* fcb  = (const float*)d_in[2];   // (512,)
    const float* tsc  = (const float*)d_in[3];   // (128, 784)
    const float* gum  = (const float*)d_in[4];   // (8, 128, 16)
    float* out = (float*)d_out;

    cudaFuncSetAttribute(gemm_kernel, cudaFuncAttributeMaxDynamicSharedMemorySize, SM_TOTAL);

    wt_kernel<<<dim3(KDIM / 32, NDIM / 32), dim3(32, 8)>>>(fcw);
    gemm_kernel<<<dim3(NDIM / N_TILE, MTOT / M_TILE), NTHR, SM_TOTAL>>>(swin, fcb);
    ts_kernel<<<(MTOT + 255) / 256, 256>>>(tsc);
    select_kernel<<<BATCH, TOK>>>(gum, out, (long long)out_size);
    gather_kernel<<<dim3(NSEL, BATCH), 256>>>(out);
    (void)in_sizes; (void)n_in;
}

// round 3
// speedup vs baseline: 1.5270x; 1.5270x over previous
#include <cuda_runtime.h>
#include <cuda_fp16.h>
#include <cstdint>

#define DI __device__ __forceinline__

// ---------------- problem constants ----------------
namespace {
constexpr int BATCH = 128;
constexpr int NFRM  = 16;
constexpr int TPF   = 49;
constexpr int NSEL  = 8;
constexpr int TOK   = NFRM * TPF;          // 784
constexpr int MTOT  = BATCH * TOK;         // 100352
constexpr int KDIM  = 1024;
constexpr int NDIM  = 512;

constexpr int M_TILE = 256;
constexpr int N_TILE = 128;
constexpr int KC     = 64;                 // fp16 elems per K-chunk (=128B row)
constexpr int NK     = KDIM / KC;          // 16
constexpr int NTHR   = 512;                // 16 warps: 4 (m) x 4 (n)
constexpr long long SEL_ELEMS = (long long)BATCH * NSEL * TPF * NDIM; // 25,690,112

// shared memory: 3 stages of (A 32KB + B 16KB), then bias
constexpr int STAGE_B  = 49152;
constexpr int SM_BOFF  = 32768;            // B offset within a stage
constexpr int SM_BIAS  = 3 * STAGE_B;      // 147456
constexpr int SM_TOTAL = SM_BIAS + 512;
}

// ---------------- device scratch (no runtime allocation allowed) -----------
__device__ __half g_swinh[(size_t)MTOT * KDIM];  // 205.5 MB swin in fp16
__device__ float  g_vid[(size_t)MTOT * NDIM];    // 205.5 MB vid_feats scratch
__device__ __half g_wth[NDIM * KDIM];            // fc_w transposed, fp16
__device__ float  g_part[4][MTOT];               // per-n-block sumsq partials
__device__ float  g_ts[MTOT];                    // token_score * ||row||
__device__ int    g_sel[BATCH * NSEL];           // selected frames, ascending

// ---------------- PTX helpers ----------------
DI uint32_t smem_u32(const void* p) {
    uint32_t a;
    asm("{ .reg .u64 t; cvta.to.shared.u64 t, %1; cvt.u32.u64 %0, t; }" : "=r"(a) : "l"(p));
    return a;
}
DI void ldsm4(uint32_t (&r)[4], uint32_t addr) {
    asm volatile("ldmatrix.sync.aligned.m8n8.x4.shared.b16 {%0,%1,%2,%3}, [%4];"
                 : "=r"(r[0]), "=r"(r[1]), "=r"(r[2]), "=r"(r[3]) : "r"(addr));
}
DI void mma16(float (&d)[4], const uint32_t (&a)[4], uint32_t b0, uint32_t b1) {
    asm volatile("mma.sync.aligned.m16n8k16.row.col.f32.f16.f16.f32 "
                 "{%0,%1,%2,%3}, {%4,%5,%6,%7}, {%8,%9}, {%0,%1,%2,%3};"
                 : "+f"(d[0]), "+f"(d[1]), "+f"(d[2]), "+f"(d[3])
                 : "r"(a[0]), "r"(a[1]), "r"(a[2]), "r"(a[3]), "r"(b0), "r"(b1));
}
DI void cp16(uint32_t dst, const void* src) {
    asm volatile("cp.async.cg.shared.global [%0], [%1], 16;" :: "r"(dst), "l"(src) : "memory");
}
#define CP_COMMIT() asm volatile("cp.async.commit_group;" ::: "memory")
#define CP_WAIT1()  asm volatile("cp.async.wait_group 1;" ::: "memory")

// ---------------- kernel 0: swin f32 -> fp16 ----------------
__global__ void conv_kernel(const float* __restrict__ s) {
    size_t i = ((size_t)blockIdx.x * blockDim.x + threadIdx.x) * 8;
    float4 v0 = *(const float4*)(s + i);
    float4 v1 = *(const float4*)(s + i + 4);
    __half2 h0 = __floats2half2_rn(v0.x, v0.y);
    __half2 h1 = __floats2half2_rn(v0.z, v0.w);
    __half2 h2 = __floats2half2_rn(v1.x, v1.y);
    __half2 h3 = __floats2half2_rn(v1.z, v1.w);
    uint4 o;
    o.x = *(uint32_t*)&h0; o.y = *(uint32_t*)&h1;
    o.z = *(uint32_t*)&h2; o.w = *(uint32_t*)&h3;
    *(uint4*)(&g_swinh[i]) = o;
}

// ---------------- kernel 1: transpose + fp16-round fc_w ----------------
__global__ void wt_kernel(const float* __restrict__ w) {
    __shared__ float t[32][33];
    int k0 = blockIdx.x * 32, n0 = blockIdx.y * 32;
    int x = threadIdx.x, y = threadIdx.y;
    #pragma unroll
    for (int dy = 0; dy < 32; dy += 8)
        t[y + dy][x] = w[(size_t)(k0 + y + dy) * NDIM + n0 + x];
    __syncthreads();
    #pragma unroll
    for (int dy = 0; dy < 32; dy += 8)
        g_wth[(size_t)(n0 + y + dy) * KDIM + k0 + x] = __float2half_rn(t[x][y + dy]);
}

// ---------------- kernel 2: fp16 mma.sync GEMM (256x128 tile) --------------
DI void issue_chunk(uint32_t sb, int stage, int m0, int gn0, int kc, int tid) {
    uint32_t ab = sb + stage * STAGE_B;
    uint32_t bb = ab + SM_BOFF;
    const __half* asrc = g_swinh + (size_t)m0 * KDIM + kc * KC;
    const __half* bsrc = g_wth + (size_t)gn0 * KDIM + kc * KC;
    #pragma unroll
    for (int s = 0; s < 4; s++) {
        int slot = tid + s * NTHR;
        int row = slot >> 3, q = slot & 7;
        cp16(ab + row * 128 + (((uint32_t)q ^ (row & 7)) << 4),
             asrc + (size_t)row * KDIM + q * 8);
    }
    #pragma unroll
    for (int s = 0; s < 2; s++) {
        int slot = tid + s * NTHR;
        int row = slot >> 3, q = slot & 7;
        cp16(bb + row * 128 + (((uint32_t)q ^ (row & 7)) << 4),
             bsrc + (size_t)row * KDIM + q * 8);
    }
    CP_COMMIT();
}

__global__ void __launch_bounds__(NTHR, 1)
gemm_kernel(const float* __restrict__ fcb) {
    extern __shared__ char smem[];
    uint32_t sb = smem_u32(smem);
    int tid = threadIdx.x;
    int w = tid >> 5, l = tid & 31;
    int nb = blockIdx.x;
    int m0 = blockIdx.y * M_TILE;
    int gn0 = nb * N_TILE;
    int wm = (w >> 2) * 64;        // warp m offset
    int wn = (w & 3) * 32;         // warp n offset

    if (tid < N_TILE) *(float*)(smem + SM_BIAS + tid * 4) = fcb[gn0 + tid];

    float acc[4][4][4];
    #pragma unroll
    for (int mt = 0; mt < 4; mt++)
        #pragma unroll
        for (int nt = 0; nt < 4; nt++)
            #pragma unroll
            for (int j = 0; j < 4; j++) acc[mt][nt][j] = 0.f;

    // per-lane ldmatrix offsets
    uint32_t lx   = (uint32_t)(l & 7);
    uint32_t apar = (uint32_t)(l >> 4);          // A k-half parity
    uint32_t bpar = (uint32_t)((l >> 3) & 1);    // B k-half parity
    uint32_t a_off[4], b_off[2];
    {
        uint32_t arow = (uint32_t)(wm + (l & 15));
        #pragma unroll
        for (int mt = 0; mt < 4; mt++) a_off[mt] = (arow + mt * 16) * 128u;
        uint32_t brow = (uint32_t)(wn + (l & 7) + ((l & 16) >> 1));
        #pragma unroll
        for (int g = 0; g < 2; g++) b_off[g] = (brow + g * 16) * 128u + SM_BOFF;
    }

    issue_chunk(sb, 0, m0, gn0, 0, tid);
    issue_chunk(sb, 1, m0, gn0, 1, tid);

    int cst = 0, ist = 2;                        // compute / issue stage counters
    for (int i = 0; i < NK; i++) {
        CP_WAIT1();                              // chunk i resident
        __syncthreads();                         // all warps done with chunk i-1
        if (i + 2 < NK) issue_chunk(sb, ist, m0, gn0, i + 2, tid);
        else CP_COMMIT();                        // keep group count aligned
        if (++ist == 3) ist = 0;

        uint32_t ab = sb + cst * STAGE_B;
        #pragma unroll
        for (int ks = 0; ks < 4; ks++) {
            uint32_t af[4][4], bfr[2][4];
            uint32_t ca = ((2u * ks + apar) ^ lx) << 4;
            uint32_t cb = ((2u * ks + bpar) ^ lx) << 4;
            #pragma unroll
            for (int mt = 0; mt < 4; mt++) ldsm4(af[mt], ab + a_off[mt] + ca);
            #pragma unroll
            for (int g = 0; g < 2; g++)  ldsm4(bfr[g], ab + b_off[g] + cb);
            #pragma unroll
            for (int mt = 0; mt < 4; mt++)
                #pragma unroll
                for (int nt = 0; nt < 4; nt++)
                    mma16(acc[mt][nt], af[mt],
                          bfr[nt >> 1][(nt & 1) * 2], bfr[nt >> 1][(nt & 1) * 2 + 1]);
        }
        if (++cst == 3) cst = 0;
    }
    __syncthreads();   // protect smem reuse below from in-flight ldmatrix

    // ---- epilogue: bias, vid write, per-row sumsq ----
    const float* sbias = (const float*)(smem + SM_BIAS);
    float* part = (float*)smem;    // [256][4]
    #pragma unroll
    for (int mt = 0; mt < 4; mt++) {
        int r0 = wm + mt * 16 + (l >> 2);
        float s0 = 0.f, s1 = 0.f;
        #pragma unroll
        for (int nt = 0; nt < 4; nt++) {
            int colL = wn + nt * 8 + (l & 3) * 2;
            float b0 = sbias[colL], b1 = sbias[colL + 1];
            float v0 = acc[mt][nt][0] + b0, v1 = acc[mt][nt][1] + b1;
            float v2 = acc[mt][nt][2] + b0, v3 = acc[mt][nt][3] + b1;
            s0 += v0 * v0 + v1 * v1;
            s1 += v2 * v2 + v3 * v3;
            size_t g0 = (size_t)(m0 + r0) * NDIM + gn0 + colL;
            *(float2*)(g_vid + g0) = make_float2(v0, v1);
            *(float2*)(g_vid + g0 + 8 * NDIM) = make_float2(v2, v3);
        }
        s0 += __shfl_xor_sync(0xFFFFFFFFu, s0, 1);
        s0 += __shfl_xor_sync(0xFFFFFFFFu, s0, 2);
        s1 += __shfl_xor_sync(0xFFFFFFFFu, s1, 1);
        s1 += __shfl_xor_sync(0xFFFFFFFFu, s1, 2);
        if ((l & 3) == 0) {
            part[r0 * 4 + (w & 3)] = s0;
            part[(r0 + 8) * 4 + (w & 3)] = s1;
        }
    }
    __syncthreads();
    if (tid < M_TILE) {
        float s = part[tid * 4] + part[tid * 4 + 1] + part[tid * 4 + 2] + part[tid * 4 + 3];
        g_part[nb][m0 + tid] = s;
    }
}

// ---------------- kernel 2b: finish token scores ----------------
__global__ void ts_kernel(const float* __restrict__ tsc) {
    int t = blockIdx.x * 256 + threadIdx.x;
    if (t < MTOT) {
        float s = g_part[0][t] + g_part[1][t] + g_part[2][t] + g_part[3][t];
        g_ts[t] = tsc[t] * sqrtf(s);
    }
}

// ---------------- kernel 3: frame scores + gumbel selection ----------------
__global__ void select_kernel(const float* __restrict__ gumbel,
                              float* __restrict__ out, long long out_elems) {
    __shared__ float tsh[TOK];
    __shared__ float fsh[NFRM];
    int b = blockIdx.x, t = threadIdx.x;   // 128 threads
    for (int i = t; i < TOK; i += 128) tsh[i] = g_ts[b * TOK + i];
    __syncthreads();
    if (t < NFRM) {
        float s = 0.f;
        #pragma unroll
        for (int j = 0; j < TPF; j++) s += tsh[t * TPF + j];
        fsh[t] = s;
    }
    __syncthreads();
    if (t == 0) {
        const float NEG_INF = __int_as_float(0xff800000);
        float tot = 0.f;
        for (int f = 0; f < NFRM; f++) tot += fsh[f];
        float fs[NFRM], sc[NFRM], sel[NFRM];
        for (int f = 0; f < NFRM; f++) { fs[f] = fsh[f] / tot; sc[f] = fs[f]; sel[f] = 0.f; }
        for (int s = 0; s < NSEL; s++) {
            const float* g = gumbel + ((size_t)s * BATCH + b) * NFRM;
            float best = NEG_INF; int bi = 0;
            for (int f = 0; f < NFRM; f++) {
                float v = (sel[f] > 0.f) ? NEG_INF : (sc[f] + g[f]);
                if (v > best) { best = v; bi = f; }   // strict > == first-max argmax
            }
            sel[bi] = 1.f; sc[bi] = 0.f;
        }
        float rest = 0.f;
        for (int f = 0; f < NFRM; f++) rest += fs[f] * (1.f - sel[f]);
        float label = (rest >= 0.5f) ? 1.f : 0.f;
        int c = 0;
        for (int f = 0; f < NFRM; f++)
            if (sel[f] > 0.f) g_sel[b * NSEL + (c++)] = f;     // ascending
        if (out_elems >= SEL_ELEMS + BATCH + (long long)BATCH * NFRM) {
            out[SEL_ELEMS + b] = label;
            float* fsp = out + SEL_ELEMS + BATCH;
            for (int f = 0; f < NFRM; f++) fsp[b * NFRM + f] = sel[f];
        }
    }
}

// ---------------- kernel 4: gather selected frames ----------------
__global__ void gather_kernel(float* __restrict__ out) {
    int j = blockIdx.x, b = blockIdx.y;
    int f = g_sel[b * NSEL + j];
    const float4* src = (const float4*)(g_vid + ((size_t)b * TOK + (size_t)f * TPF) * NDIM);
    float4* dst = (float4*)(out + ((size_t)b * (NSEL * TPF) + (size_t)j * TPF) * NDIM);
    constexpr int N4 = TPF * NDIM / 4;   // 6272
    for (int i = threadIdx.x; i < N4; i += blockDim.x) dst[i] = src[i];
}

// ---------------- launch ----------------
extern "C" void kernel_launch(void* const* d_in, const int* in_sizes, int n_in,
                              void* d_out, int out_size) {
    const float* swin = (const float*)d_in[0];   // (128, 784, 1024)
    const float* fcw  = (const float*)d_in[1];   // (1024, 512)
    const float* fcb  = (const float*)d_in[2];   // (512,)
    const float* tsc  = (const float*)d_in[3];   // (128, 784)
    const float* gum  = (const float*)d_in[4];   // (8, 128, 16)
    float* out = (float*)d_out;

    cudaFuncSetAttribute(gemm_kernel, cudaFuncAttributeMaxDynamicSharedMemorySize, SM_TOTAL);

    conv_kernel<<<(int)(((size_t)MTOT * KDIM / 8) / 256), 256>>>(swin);
    wt_kernel<<<dim3(KDIM / 32, NDIM / 32), dim3(32, 8)>>>(fcw);
    gemm_kernel<<<dim3(NDIM / N_TILE, MTOT / M_TILE), NTHR, SM_TOTAL>>>(fcb);
    ts_kernel<<<(MTOT + 255) / 256, 256>>>(tsc);
    select_kernel<<<BATCH, 128>>>(gum, out, (long long)out_size);
    gather_kernel<<<dim3(NSEL, BATCH), 256>>>(out);
    (void)in_sizes; (void)n_in;
}

// round 4
// speedup vs baseline: 1.5913x; 1.0421x over previous
#include <cuda_runtime.h>
#include <cuda_fp16.h>
#include <cstdint>

#define DI __device__ __forceinline__

// ---------------- problem constants ----------------
namespace {
constexpr int BATCH = 128;
constexpr int NFRM  = 16;
constexpr int TPF   = 49;
constexpr int NSEL  = 8;
constexpr int TOK   = NFRM * TPF;          // 784
constexpr int MTOT  = BATCH * TOK;         // 100352
constexpr int KDIM  = 1024;
constexpr int NDIM  = 512;

constexpr int M_TILE = 256;
constexpr int N_TILE = 128;
constexpr int KC     = 64;                 // fp16 elems per K-chunk (=128B row)
constexpr int NK     = KDIM / KC;          // 16
constexpr int NTHR   = 512;                // 16 warps: 4 (m) x 4 (n)
constexpr long long SEL_ELEMS = (long long)BATCH * NSEL * TPF * NDIM; // 25,690,112

// shared memory: 2 stages of (A 32KB + B 16KB), then bias
constexpr int STAGE_B  = 49152;
constexpr int SM_BOFF  = 32768;            // B offset within a stage
constexpr int SM_BIAS  = 2 * STAGE_B;      // 98304
constexpr int SM_TOTAL = SM_BIAS + 512;
}

// ---------------- device scratch (no runtime allocation allowed) -----------
__device__ float  g_vid[(size_t)MTOT * NDIM];    // 205.5 MB vid_feats scratch
__device__ __half g_wth[NDIM * KDIM];            // fc_w transposed, fp16
__device__ float  g_part[4][MTOT];               // per-n-block sumsq partials
__device__ float  g_ts[MTOT];                    // token_score * ||row||
__device__ int    g_sel[BATCH * NSEL];           // selected frames, ascending

// ---------------- PTX helpers ----------------
DI uint32_t smem_u32(const void* p) {
    uint32_t a;
    asm("{ .reg .u64 t; cvta.to.shared.u64 t, %1; cvt.u32.u64 %0, t; }" : "=r"(a) : "l"(p));
    return a;
}
DI void ldsm4(uint32_t (&r)[4], uint32_t addr) {
    asm volatile("ldmatrix.sync.aligned.m8n8.x4.shared.b16 {%0,%1,%2,%3}, [%4];"
                 : "=r"(r[0]), "=r"(r[1]), "=r"(r[2]), "=r"(r[3]) : "r"(addr));
}
DI void mma16(float (&d)[4], const uint32_t (&a)[4], uint32_t b0, uint32_t b1) {
    asm volatile("mma.sync.aligned.m16n8k16.row.col.f32.f16.f16.f32 "
                 "{%0,%1,%2,%3}, {%4,%5,%6,%7}, {%8,%9}, {%0,%1,%2,%3};"
                 : "+f"(d[0]), "+f"(d[1]), "+f"(d[2]), "+f"(d[3])
                 : "r"(a[0]), "r"(a[1]), "r"(a[2]), "r"(a[3]), "r"(b0), "r"(b1));
}
DI void cp16(uint32_t dst, const void* src) {
    asm volatile("cp.async.cg.shared.global [%0], [%1], 16;" :: "r"(dst), "l"(src) : "memory");
}
#define CP_COMMIT() asm volatile("cp.async.commit_group;" ::: "memory")
#define CP_WAIT0()  asm volatile("cp.async.wait_group 0;" ::: "memory")

// ---------------- kernel 1: transpose + fp16-round fc_w ----------------
__global__ void wt_kernel(const float* __restrict__ w) {
    __shared__ float t[32][33];
    int k0 = blockIdx.x * 32, n0 = blockIdx.y * 32;
    int x = threadIdx.x, y = threadIdx.y;
    #pragma unroll
    for (int dy = 0; dy < 32; dy += 8)
        t[y + dy][x] = w[(size_t)(k0 + y + dy) * NDIM + n0 + x];
    __syncthreads();
    #pragma unroll
    for (int dy = 0; dy < 32; dy += 8)
        g_wth[(size_t)(n0 + y + dy) * KDIM + k0 + x] = __float2half_rn(t[x][y + dy]);
}

// ---------------- kernel 2: fused cvt + fp16 mma.sync GEMM (256x128) -------
// A chunk (256 rows x 64 f16 = 32KB): loaded as f32 from swin, converted in
// regs, stored swizzled. Split into two 16-reg halves around the ks steps.
DI void ldA_half(const float* __restrict__ swin, int m0, int kb, int tid,
                 int h, float4 (&pa)[4]) {
    #pragma unroll
    for (int s = 0; s < 2; s++) {
        int slot = tid + (h * 2 + s) * NTHR;
        int row = slot >> 3, q = slot & 7;
        const float* p = swin + (size_t)(m0 + row) * KDIM + kb + q * 8;
        pa[s * 2]     = *(const float4*)p;
        pa[s * 2 + 1] = *(const float4*)(p + 4);
    }
}
DI void stA_half(char* abuf, int tid, int h, const float4 (&pa)[4]) {
    #pragma unroll
    for (int s = 0; s < 2; s++) {
        int slot = tid + (h * 2 + s) * NTHR;
        int row = slot >> 3, q = slot & 7;
        __half2 h0 = __floats2half2_rn(pa[s*2].x,   pa[s*2].y);
        __half2 h1 = __floats2half2_rn(pa[s*2].z,   pa[s*2].w);
        __half2 h2 = __floats2half2_rn(pa[s*2+1].x, pa[s*2+1].y);
        __half2 h3 = __floats2half2_rn(pa[s*2+1].z, pa[s*2+1].w);
        uint4 o;
        o.x = *(uint32_t*)&h0; o.y = *(uint32_t*)&h1;
        o.z = *(uint32_t*)&h2; o.w = *(uint32_t*)&h3;
        *(uint4*)(abuf + row * 128 + (((uint32_t)q ^ (row & 7)) << 4)) = o;
    }
}
DI void issueB(uint32_t bb, int gn0, int kb, int tid) {
    #pragma unroll
    for (int s = 0; s < 2; s++) {
        int slot = tid + s * NTHR;
        int row = slot >> 3, q = slot & 7;
        cp16(bb + row * 128 + (((uint32_t)q ^ (row & 7)) << 4),
             g_wth + (size_t)(gn0 + row) * KDIM + kb + q * 8);
    }
    CP_COMMIT();
}

__global__ void __launch_bounds__(NTHR, 1)
gemm_kernel(const float* __restrict__ swin, const float* __restrict__ fcb) {
    extern __shared__ char smem[];
    uint32_t sb = smem_u32(smem);
    int tid = threadIdx.x;
    int w = tid >> 5, l = tid & 31;
    int nb = blockIdx.x;
    int m0 = blockIdx.y * M_TILE;
    int gn0 = nb * N_TILE;
    int wm = (w >> 2) * 64;        // warp m offset
    int wn = (w & 3) * 32;         // warp n offset

    if (tid < N_TILE) *(float*)(smem + SM_BIAS + tid * 4) = fcb[gn0 + tid];

    float acc[4][4][4];
    #pragma unroll
    for (int mt = 0; mt < 4; mt++)
        #pragma unroll
        for (int nt = 0; nt < 4; nt++)
            #pragma unroll
            for (int j = 0; j < 4; j++) acc[mt][nt][j] = 0.f;

    // per-lane ldmatrix offsets (verified mapping from prior rounds)
    uint32_t lx   = (uint32_t)(l & 7);
    uint32_t apar = (uint32_t)(l >> 4);          // A k-half parity
    uint32_t bpar = (uint32_t)((l >> 3) & 1);    // B k-half parity
    uint32_t a_off[4], b_off[2];
    {
        uint32_t arow = (uint32_t)(wm + (l & 15));
        #pragma unroll
        for (int mt = 0; mt < 4; mt++) a_off[mt] = (arow + mt * 16) * 128u;
        uint32_t brow = (uint32_t)(wn + (l & 7) + ((l & 16) >> 1));
        #pragma unroll
        for (int g = 0; g < 2; g++) b_off[g] = (brow + g * 16) * 128u + SM_BOFF;
    }

    // ---- prologue: chunk 0 into stage 0 ----
    {
        float4 p0[4], p1[4];
        ldA_half(swin, m0, 0, tid, 0, p0);
        ldA_half(swin, m0, 0, tid, 1, p1);
        issueB(sb + SM_BOFF, gn0, 0, tid);
        stA_half(smem, tid, 0, p0);
        stA_half(smem, tid, 1, p1);
        CP_WAIT0();
        __syncthreads();
    }

    int buf = 0;
    for (int i = 0; i < NK; i++) {
        bool pf = (i + 1 < NK);
        int kb = (i + 1) * KC;
        char* anext = smem + (buf ^ 1) * STAGE_B;
        float4 pa[4];
        if (pf) {
            issueB(sb + (buf ^ 1) * STAGE_B + SM_BOFF, gn0, kb, tid);
            ldA_half(swin, m0, kb, tid, 0, pa);
        }

        uint32_t ab = sb + buf * STAGE_B;
        #pragma unroll
        for (int ks = 0; ks < 4; ks++) {
            if (pf && ks == 2) {               // mid-chunk: rotate prefetch half
                stA_half(anext, tid, 0, pa);
                ldA_half(swin, m0, kb, tid, 1, pa);
            }
            uint32_t af[4][4], bfr[2][4];
            uint32_t ca = ((2u * ks + apar) ^ lx) << 4;
            uint32_t cb = ((2u * ks + bpar) ^ lx) << 4;
            #pragma unroll
            for (int mt = 0; mt < 4; mt++) ldsm4(af[mt], ab + a_off[mt] + ca);
            #pragma unroll
            for (int g = 0; g < 2; g++)  ldsm4(bfr[g], ab + b_off[g] + cb);
            #pragma unroll
            for (int mt = 0; mt < 4; mt++)
                #pragma unroll
                for (int nt = 0; nt < 4; nt++)
                    mma16(acc[mt][nt], af[mt],
                          bfr[nt >> 1][(nt & 1) * 2], bfr[nt >> 1][(nt & 1) * 2 + 1]);
        }
        if (pf) stA_half(anext, tid, 1, pa);
        CP_WAIT0();
        __syncthreads();
        buf ^= 1;
    }

    // ---- epilogue: bias, vid write, per-row sumsq ----
    const float* sbias = (const float*)(smem + SM_BIAS);
    float* part = (float*)smem;    // [256][4] reuse (post-barrier)
    #pragma unroll
    for (int mt = 0; mt < 4; mt++) {
        int r0 = wm + mt * 16 + (l >> 2);
        float s0 = 0.f, s1 = 0.f;
        #pragma unroll
        for (int nt = 0; nt < 4; nt++) {
            int colL = wn + nt * 8 + (l & 3) * 2;
            float b0 = sbias[colL], b1 = sbias[colL + 1];
            float v0 = acc[mt][nt][0] + b0, v1 = acc[mt][nt][1] + b1;
            float v2 = acc[mt][nt][2] + b0, v3 = acc[mt][nt][3] + b1;
            s0 += v0 * v0 + v1 * v1;
            s1 += v2 * v2 + v3 * v3;
            size_t g0 = (size_t)(m0 + r0) * NDIM + gn0 + colL;
            *(float2*)(g_vid + g0) = make_float2(v0, v1);
            *(float2*)(g_vid + g0 + 8 * NDIM) = make_float2(v2, v3);
        }
        s0 += __shfl_xor_sync(0xFFFFFFFFu, s0, 1);
        s0 += __shfl_xor_sync(0xFFFFFFFFu, s0, 2);
        s1 += __shfl_xor_sync(0xFFFFFFFFu, s1, 1);
        s1 += __shfl_xor_sync(0xFFFFFFFFu, s1, 2);
        if ((l & 3) == 0) {
            part[r0 * 4 + (w & 3)] = s0;
            part[(r0 + 8) * 4 + (w & 3)] = s1;
        }
    }
    __syncthreads();
    if (tid < M_TILE) {
        float s = part[tid * 4] + part[tid * 4 + 1] + part[tid * 4 + 2] + part[tid * 4 + 3];
        g_part[nb][m0 + tid] = s;
    }
}

// ---------------- kernel 2b: finish token scores ----------------
__global__ void ts_kernel(const float* __restrict__ tsc) {
    int t = blockIdx.x * 256 + threadIdx.x;
    if (t < MTOT) {
        float s = g_part[0][t] + g_part[1][t] + g_part[2][t] + g_part[3][t];
        g_ts[t] = tsc[t] * sqrtf(s);
    }
}

// ---------------- kernel 3: frame scores + gumbel selection ----------------
__global__ void select_kernel(const float* __restrict__ gumbel,
                              float* __restrict__ out, long long out_elems) {
    __shared__ float tsh[TOK];
    __shared__ float fsh[NFRM];
    int b = blockIdx.x, t = threadIdx.x;   // 128 threads
    for (int i = t; i < TOK; i += 128) tsh[i] = g_ts[b * TOK + i];
    __syncthreads();
    if (t < NFRM) {
        float s = 0.f;
        #pragma unroll
        for (int j = 0; j < TPF; j++) s += tsh[t * TPF + j];
        fsh[t] = s;
    }
    __syncthreads();
    if (t == 0) {
        const float NEG_INF = __int_as_float(0xff800000);
        float tot = 0.f;
        for (int f = 0; f < NFRM; f++) tot += fsh[f];
        float fs[NFRM], sc[NFRM], sel[NFRM];
        for (int f = 0; f < NFRM; f++) { fs[f] = fsh[f] / tot; sc[f] = fs[f]; sel[f] = 0.f; }
        for (int s = 0; s < NSEL; s++) {
            const float* g = gumbel + ((size_t)s * BATCH + b) * NFRM;
            float best = NEG_INF; int bi = 0;
            for (int f = 0; f < NFRM; f++) {
                float v = (sel[f] > 0.f) ? NEG_INF : (sc[f] + g[f]);
                if (v > best) { best = v; bi = f; }   // strict > == first-max argmax
            }
            sel[bi] = 1.f; sc[bi] = 0.f;
        }
        float rest = 0.f;
        for (int f = 0; f < NFRM; f++) rest += fs[f] * (1.f - sel[f]);
        float label = (rest >= 0.5f) ? 1.f : 0.f;
        int c = 0;
        for (int f = 0; f < NFRM; f++)
            if (sel[f] > 0.f) g_sel[b * NSEL + (c++)] = f;     // ascending
        if (out_elems >= SEL_ELEMS + BATCH + (long long)BATCH * NFRM) {
            out[SEL_ELEMS + b] = label;
            float* fsp = out + SEL_ELEMS + BATCH;
            for (int f = 0; f < NFRM; f++) fsp[b * NFRM + f] = sel[f];
        }
    }
}

// ---------------- kernel 4: gather selected frames ----------------
__global__ void gather_kernel(float* __restrict__ out) {
    int j = blockIdx.x, b = blockIdx.y;
    int f = g_sel[b * NSEL + j];
    const float4* src = (const float4*)(g_vid + ((size_t)b * TOK + (size_t)f * TPF) * NDIM);
    float4* dst = (float4*)(out + ((size_t)b * (NSEL * TPF) + (size_t)j * TPF) * NDIM);
    constexpr int N4 = TPF * NDIM / 4;   // 6272
    for (int i = threadIdx.x; i < N4; i += blockDim.x) dst[i] = src[i];
}

// ---------------- launch ----------------
extern "C" void kernel_launch(void* const* d_in, const int* in_sizes, int n_in,
                              void* d_out, int out_size) {
    const float* swin = (const float*)d_in[0];   // (128, 784, 1024)
    const float* fcw  = (const float*)d_in[1];   // (1024, 512)
    const float* fcb  = (const float*)d_in[2];   // (512,)
    const float* tsc  = (const float*)d_in[3];   // (128, 784)
    const float* gum  = (const float*)d_in[4];   // (8, 128, 16)
    float* out = (float*)d_out;

    cudaFuncSetAttribute(gemm_kernel, cudaFuncAttributeMaxDynamicSharedMemorySize, SM_TOTAL);

    wt_kernel<<<dim3(KDIM / 32, NDIM / 32), dim3(32, 8)>>>(fcw);
    gemm_kernel<<<dim3(NDIM / N_TILE, MTOT / M_TILE), NTHR, SM_TOTAL>>>(swin, fcb);
    ts_kernel<<<(MTOT + 255) / 256, 256>>>(tsc);
    select_kernel<<<BATCH, 128>>>(gum, out, (long long)out_size);
    gather_kernel<<<dim3(NSEL, BATCH), 256>>>(out);
    (void)in_sizes; (void)n_in;
}